// round 5
// baseline (speedup 1.0000x reference)
#include <cuda_runtime.h>
#include <math.h>
#include <stdint.h>

// Problem constants (fixed by the dataset)
#define B_   32
#define D_   1024
#define N_   65536
#define K_   4096
#define H_   8
#define HD_  128
#define NSPLIT 16

typedef unsigned long long u64;
typedef unsigned int       u32;

// ---------------- scratch (static device globals; no allocation) -------------
__device__ u32  g_hist16[65536];
__device__ int  g_T16;
__device__ int  g_cumAbove;
__device__ int  g_num_cand;
__device__ int  g_sel_count;
__device__ u64  g_cand[N_];
__device__ u64  g_sel_ck[K_];
__device__ int  g_sorted_idx[K_];
__device__ float g_kproj[K_ * D_];
__device__ float g_vproj[K_ * D_];
__device__ float g_qproj[B_ * D_];
__device__ float g_attn[B_ * H_ * K_];
__device__ float g_ctx_part[NSPLIT * B_ * D_];
__device__ float g_ctx[B_ * D_];

__device__ __forceinline__ u32 f2tf32(float f) {
    u32 u;
    asm("cvt.rna.tf32.f32 %0, %1;" : "=r"(u) : "f"(f));
    return u;
}

// m16n8k8 tf32 MMA (base PTX, sm_80+; no sm_103a-gated features)
__device__ __forceinline__ void mma_tf32(
    float& c0, float& c1, float& c2, float& c3,
    u32 a0, u32 a1, u32 a2, u32 a3, u32 b0, u32 b1)
{
    asm volatile(
        "mma.sync.aligned.m16n8k8.row.col.f32.tf32.tf32.f32 "
        "{%0,%1,%2,%3}, {%4,%5,%6,%7}, {%8,%9}, {%0,%1,%2,%3};"
        : "+f"(c0), "+f"(c1), "+f"(c2), "+f"(c3)
        : "r"(a0), "r"(a1), "r"(a2), "r"(a3), "r"(b0), "r"(b1));
}

// Composite key: (monotone(float) << 32) | (0xFFFFFFFF - index)
// Descending composite order == (value desc, index asc) == jax.lax.top_k order.
__device__ __forceinline__ u64 make_ck(float f, int i) {
    u32 x = __float_as_uint(f);
    u32 t = (x & 0x80000000u) ? ~x : (x | 0x80000000u);
    return ((u64)t << 32) | (u32)(0xFFFFFFFFu - (u32)i);
}

// ---------------- selection ----------------
__global__ void k_zero16() {
    int stride = gridDim.x * blockDim.x;
    for (int i = blockIdx.x * blockDim.x + threadIdx.x; i < 65536; i += stride)
        g_hist16[i] = 0;
    if (blockIdx.x == 0 && threadIdx.x == 0) { g_num_cand = 0; g_sel_count = 0; }
}

__global__ void k_hist16(const float* __restrict__ prio) {
    int stride = gridDim.x * blockDim.x;
    for (int i = blockIdx.x * blockDim.x + threadIdx.x; i < N_; i += stride) {
        u64 ck = make_ck(prio[i], i);
        atomicAdd(&g_hist16[(u32)(ck >> 48)], 1u);
    }
}

// Single CTA, 1024 threads: find the 16-bit threshold bin by descending scan.
__global__ void k_findbin() {
    __shared__ u32 strip[1024];
    int t = threadIdx.x;
    int base = 65535 - t * 64;
    u32 s = 0;
    for (int i = 0; i < 64; i++) s += g_hist16[base - i];
    strip[t] = s;
    __syncthreads();
    if (t == 0) {
        u32 cum = 0; int st = 1023;
        for (int i = 0; i < 1024; i++) {
            if (cum + strip[i] >= (u32)K_) { st = i; break; }
            cum += strip[i];
        }
        int b = 65535 - st * 64;
        for (int i = 0; i < 64; i++) {
            u32 h = g_hist16[b - i];
            if (cum + h >= (u32)K_) { g_T16 = b - i; g_cumAbove = (int)cum; break; }
            cum += h;
        }
    }
}

__global__ void k_compact16(const float* __restrict__ prio) {
    int T16 = g_T16;
    int stride = gridDim.x * blockDim.x;
    for (int i = blockIdx.x * blockDim.x + threadIdx.x; i < N_; i += stride) {
        u64 ck = make_ck(prio[i], i);
        int k16 = (int)(u32)(ck >> 48);
        if (k16 > T16) {
            int p = atomicAdd(&g_sel_count, 1);
            g_sel_ck[p] = ck;
        } else if (k16 == T16) {
            int p = atomicAdd(&g_num_cand, 1);
            g_cand[p] = ck;
        }
    }
}

// Single CTA: refine the low 48 bits among the (tiny) candidate set.
__global__ void k_selfin48() {
    __shared__ u64 sc[4096];
    __shared__ u32 hist[256];
    __shared__ u64 s_pref;
    __shared__ int s_R;
    int t = threadIdx.x;  // 256
    int nc = g_num_cand;
    bool inSm = (nc <= 4096);
    if (inSm) for (int i = t; i < nc; i += 256) sc[i] = g_cand[i];
    if (t == 0) {
        s_pref = ((u64)(u32)g_T16) << 48;
        s_R = K_ - g_cumAbove;
    }
    __syncthreads();
    for (int shift = 40; shift >= 0; shift -= 8) {
        hist[t] = 0;
        __syncthreads();
        u64 pref  = s_pref;
        u64 hmask = (~0ULL) << (shift + 8);
        for (int i = t; i < nc; i += 256) {
            u64 ck = inSm ? sc[i] : g_cand[i];
            if ((ck & hmask) == pref)
                atomicAdd(&hist[(u32)(ck >> shift) & 0xFFu], 1u);
        }
        __syncthreads();
        if (t == 0) {
            int R = s_R, cum = 0, b = 0;
            for (int bb = 255; bb >= 0; bb--) {
                if (cum + (int)hist[bb] >= R) { b = bb; break; }
                cum += (int)hist[bb];
            }
            s_pref = pref | (((u64)(u32)b) << shift);
            s_R = R - cum;
        }
        __syncthreads();
    }
    u64 T = s_pref;
    for (int i = t; i < nc; i += 256) {
        u64 ck = inSm ? sc[i] : g_cand[i];
        if (ck >= T) {
            int p = atomicAdd(&g_sel_count, 1);
            g_sel_ck[p] = ck;
        }
    }
}

// Rank sort: one warp per selected element, pairwise count of larger keys.
__global__ void k_rank() {
    __shared__ u64 s_ck[K_];  // 32 KB
    int t = threadIdx.x;
    for (int i = t; i < K_; i += blockDim.x) s_ck[i] = g_sel_ck[i];
    __syncthreads();
    int warp = t >> 5, lane = t & 31;
    int i = blockIdx.x * 8 + warp;
    u64 my = s_ck[i];
    int cnt = 0;
    for (int j = lane; j < K_; j += 32)
        cnt += (s_ck[j] > my) ? 1 : 0;
#pragma unroll
    for (int o = 16; o > 0; o >>= 1) cnt += __shfl_down_sync(0xFFFFFFFFu, cnt, o);
    if (lane == 0)
        g_sorted_idx[cnt] = (int)(0xFFFFFFFFu - (u32)(my & 0xFFFFFFFFull));
}

// ============ K/V projection via mma.sync tf32 (m16n8k8) ============
// CTA tile 128x128, 8 warps, warp tile 64x32 (4x4 frags of 16x8).
// Double-buffered smem, one __syncthreads per K=16 chunk, LDS.64 frag loads.
//
// A smem layout: As2[k][jm], jm(m) = (m/16)*16 + (m%8)*2 + (m%16)/8
//   -> fragment pair (m, m+8) adjacent words; stride 136 => conflict-free reads.
// B smem layout: Bs2[n][slot], slot(k) = (k&3)*2 + ((k&7)>>2) + (k&8)
//   -> fragment pair (k, k+4) adjacent words; stride 24 => conflict-free reads.
#define KV_CH 16
#define KV_NCH (D_ / KV_CH)   // 64

__global__ void __launch_bounds__(256, 2)
k_kvproj_mma(const float* __restrict__ buffer,
             const float* __restrict__ Wk, const float* __restrict__ bk,
             const float* __restrict__ Wv, const float* __restrict__ bv)
{
    const float* W    = blockIdx.z ? Wv : Wk;
    const float* bias = blockIdx.z ? bv : bk;
    float* out        = blockIdx.z ? g_vproj : g_kproj;
    int m0 = blockIdx.y * 128;
    int n0 = blockIdx.x * 128;

    __shared__ u32 As2[2][KV_CH][136];   // 17.4 KB
    __shared__ u32 Bs2[2][128][24];      // 24.6 KB

    int t    = threadIdx.x;
    int lane = t & 31, wid = t >> 5;
    int grp  = lane >> 2, qid = lane & 3;
    int wm   = (wid >> 2) * 64;   // 0 / 64
    int wn   = (wid & 3) * 32;    // 0 / 32 / 64 / 96

    // staging assignments
    int aRow = t >> 1, aCol = (t & 1) * 8;          // A: 128 rows x 16 k
    int jmA  = (aRow >> 4) * 16 + (aRow & 7) * 2 + ((aRow & 15) >> 3);
    int bRow = t >> 4, bCol = (t & 15) * 8;         // B: 16 k x 128 n
    int slotB = (bRow & 3) * 2 + ((bRow & 7) >> 2) + (bRow & 8);

    const float* aPtr = buffer + (size_t)g_sorted_idx[m0 + aRow] * D_ + aCol;
    const float* bPtr = W + (size_t)bRow * D_ + n0 + bCol;

    float acc[4][4][4];
#pragma unroll
    for (int i = 0; i < 4; i++)
#pragma unroll
        for (int j = 0; j < 4; j++)
#pragma unroll
            for (int q = 0; q < 4; q++) acc[i][j][q] = 0.0f;

    float ra[8], rb[8];

#define KV_LOAD(c) do { \
    int _ko = (c) * KV_CH; \
    *(float4*)&ra[0] = *(const float4*)(aPtr + _ko); \
    *(float4*)&ra[4] = *(const float4*)(aPtr + _ko + 4); \
    *(float4*)&rb[0] = *(const float4*)(bPtr + (size_t)_ko * D_); \
    *(float4*)&rb[4] = *(const float4*)(bPtr + (size_t)_ko * D_ + 4); \
} while (0)

#define KV_STORE(bf_) do { \
    _Pragma("unroll") \
    for (int q = 0; q < 8; q++) As2[bf_][aCol + q][jmA] = f2tf32(ra[q]); \
    _Pragma("unroll") \
    for (int q = 0; q < 8; q++) Bs2[bf_][bCol + q][slotB] = f2tf32(rb[q]); \
} while (0)

    KV_LOAD(0);
    KV_STORE(0);
    __syncthreads();
    KV_LOAD(1);

    for (int c = 0; c < KV_NCH; c++) {
        int buf = c & 1;
        const u32 (*As)[136] = As2[buf];
        const u32 (*Bs)[24]  = Bs2[buf];
        // compute: 2 k-steps of 8
#pragma unroll
        for (int kk = 0; kk < 16; kk += 8) {
            uint2 afLo[4], afHi[4], bfp[4];
#pragma unroll
            for (int mf = 0; mf < 4; mf++) {
                int jm = ((wm >> 4) + mf) * 16 + grp * 2;
                afLo[mf] = *(const uint2*)&As[kk + qid][jm];       // a0, a1
                afHi[mf] = *(const uint2*)&As[kk + qid + 4][jm];   // a2, a3
            }
#pragma unroll
            for (int nf = 0; nf < 4; nf++) {
                int n = wn + nf * 8 + grp;
                bfp[nf] = *(const uint2*)&Bs[n][kk + 2 * qid];     // b0, b1
            }
#pragma unroll
            for (int mf = 0; mf < 4; mf++)
#pragma unroll
                for (int nf = 0; nf < 4; nf++)
                    mma_tf32(acc[mf][nf][0], acc[mf][nf][1], acc[mf][nf][2], acc[mf][nf][3],
                             afLo[mf].x, afLo[mf].y, afHi[mf].x, afHi[mf].y,
                             bfp[nf].x, bfp[nf].y);
        }
        if (c + 1 < KV_NCH) {
            KV_STORE(buf ^ 1);
            __syncthreads();
            if (c + 2 < KV_NCH) KV_LOAD(c + 2);
        }
    }

    // epilogue: D[m][n] + bias[n]
#pragma unroll
    for (int mf = 0; mf < 4; mf++) {
#pragma unroll
        for (int nf = 0; nf < 4; nf++) {
            int n = n0 + wn + nf * 8 + 2 * qid;
            float bv0 = bias[n], bv1 = bias[n + 1];
            int r0 = m0 + wm + mf * 16 + grp;
            float2 v0 = make_float2(acc[mf][nf][0] + bv0, acc[mf][nf][1] + bv1);
            float2 v1 = make_float2(acc[mf][nf][2] + bv0, acc[mf][nf][3] + bv1);
            *(float2*)(out + (size_t)r0 * D_ + n)       = v0;
            *(float2*)(out + (size_t)(r0 + 8) * D_ + n) = v1;
        }
    }
#undef KV_LOAD
#undef KV_STORE
}

// ---------------- M=32 GEMM (q proj: mode 0, out proj: mode 1) --------------
__global__ void k_gemm32(const float* __restrict__ Aext,
                         const float* __restrict__ W,
                         const float* __restrict__ bias,
                         float* __restrict__ outext, int mode)
{
    const float* A = (mode == 0) ? Aext : g_ctx;
    float* out     = (mode == 0) ? g_qproj : outext;
    int n0 = blockIdx.x * 128;

    __shared__ float As[32][36];   // [k][b]
    __shared__ float Bs[32][128];  // [k][n]
    int t = threadIdx.x;
    float acc[4][4] = {};
    int rm = (t >> 5) * 4, rn = (t & 31) * 4;
    int ab = t >> 3, akq = (t & 7) * 4;

    for (int k0 = 0; k0 < D_; k0 += 32) {
        float4 av = *(const float4*)(A + (size_t)ab * D_ + k0 + akq);
        As[akq+0][ab]=av.x; As[akq+1][ab]=av.y; As[akq+2][ab]=av.z; As[akq+3][ab]=av.w;
#pragma unroll
        for (int p = 0; p < 4; p++) {
            int id = t + p * 256;
            int br = id >> 5, bc = (id & 31) * 4;
            *(float4*)&Bs[br][bc] = *(const float4*)(W + (size_t)(k0 + br) * D_ + n0 + bc);
        }
        __syncthreads();
#pragma unroll
        for (int kk = 0; kk < 32; kk++) {
            float a[4], b[4];
            *(float4*)&a[0] = *(const float4*)&As[kk][rm];
            *(float4*)&b[0] = *(const float4*)&Bs[kk][rn];
#pragma unroll
            for (int i = 0; i < 4; i++)
#pragma unroll
                for (int j = 0; j < 4; j++)
                    acc[i][j] += a[i] * b[j];
        }
        __syncthreads();
    }
#pragma unroll
    for (int i = 0; i < 4; i++) {
        float* op = out + (size_t)(rm + i) * D_ + n0 + rn;
#pragma unroll
        for (int j = 0; j < 4; j++)
            op[j] = acc[i][j] + bias[n0 + rn + j];
    }
}

// ---------------- scores[b,h,j] = scale * q[b,h,:] . k[j,h,:] ---------------
__global__ void k_scores() {
    int j0 = blockIdx.x * 128;
    int h  = blockIdx.y;
    __shared__ float As[32][36];   // [d][b]
    __shared__ float Bs[32][132];  // [d][j]
    int t = threadIdx.x;
    float acc[4][4] = {};
    int rm = (t >> 5) * 4, rn = (t & 31) * 4;
    int ab = t >> 3, akq = (t & 7) * 4;

    for (int d0 = 0; d0 < HD_; d0 += 32) {
        float4 av = *(const float4*)(g_qproj + (size_t)ab * D_ + h * HD_ + d0 + akq);
        As[akq+0][ab]=av.x; As[akq+1][ab]=av.y; As[akq+2][ab]=av.z; As[akq+3][ab]=av.w;
#pragma unroll
        for (int p = 0; p < 4; p++) {
            int id = t + p * 256;
            int jr = id >> 3, dq = (id & 7) * 4;
            float4 bvv = *(const float4*)(g_kproj + (size_t)(j0 + jr) * D_ + h * HD_ + d0 + dq);
            Bs[dq+0][jr]=bvv.x; Bs[dq+1][jr]=bvv.y; Bs[dq+2][jr]=bvv.z; Bs[dq+3][jr]=bvv.w;
        }
        __syncthreads();
#pragma unroll
        for (int kk = 0; kk < 32; kk++) {
            float a[4], b[4];
            *(float4*)&a[0] = *(const float4*)&As[kk][rm];
            *(float4*)&b[0] = *(const float4*)&Bs[kk][rn];
#pragma unroll
            for (int i = 0; i < 4; i++)
#pragma unroll
                for (int j = 0; j < 4; j++)
                    acc[i][j] += a[i] * b[j];
        }
        __syncthreads();
    }
    const float scale = 0.08838834764831845f;  // 128^-0.5
#pragma unroll
    for (int i = 0; i < 4; i++)
#pragma unroll
        for (int j = 0; j < 4; j++)
            g_attn[((size_t)(rm + i) * H_ + h) * K_ + j0 + rn + j] = acc[i][j] * scale;
}

// ---------------- softmax over j (in place), one CTA per (b,h) row ----------
__global__ void k_softmax() {
    int row = blockIdx.x;
    float* p = g_attn + (size_t)row * K_;
    __shared__ float sd[K_];
    __shared__ float red[256];
    int t = threadIdx.x;
    float mx = -1e30f;
    for (int i = t; i < K_; i += 256) { float v = p[i]; sd[i] = v; mx = fmaxf(mx, v); }
    red[t] = mx; __syncthreads();
    for (int o = 128; o > 0; o >>= 1) { if (t < o) red[t] = fmaxf(red[t], red[t + o]); __syncthreads(); }
    mx = red[0]; __syncthreads();
    float sum = 0.0f;
    for (int i = t; i < K_; i += 256) { float e = expf(sd[i] - mx); sd[i] = e; sum += e; }
    red[t] = sum; __syncthreads();
    for (int o = 128; o > 0; o >>= 1) { if (t < o) red[t] += red[t + o]; __syncthreads(); }
    float inv = 1.0f / red[0];
    for (int i = t; i < K_; i += 256) p[i] = sd[i] * inv;
}

// ---------------- attn_avg = mean over heads -> d_out[32768:] ---------------
__global__ void k_avg(float* __restrict__ out2) {
    int idx = blockIdx.x * blockDim.x + threadIdx.x;  // 131072 total
    int b = idx >> 12, j = idx & 4095;
    float s = 0.0f;
#pragma unroll
    for (int h = 0; h < H_; h++) s += g_attn[((size_t)b * H_ + h) * K_ + j];
    out2[(size_t)b * K_ + j] = s * 0.125f;
}

// ---------------- ctx partials: attn[b,h,:] @ v[:,h,:] over j-split ---------
__global__ void k_ctxpart() {
    int h  = blockIdx.x;       // 8
    int sp = blockIdx.y;       // 16
    int jbase = sp * (K_ / NSPLIT);   // 256 j per split
    __shared__ float As[32][36];    // [j][b]
    __shared__ float Bs[32][128];   // [j][d]
    int t = threadIdx.x;
    float acc[4][4] = {};
    int rm = (t >> 5) * 4, rn = (t & 31) * 4;
    int ab = t >> 3, ajq = (t & 7) * 4;

    for (int k0 = 0; k0 < K_ / NSPLIT; k0 += 32) {
        float4 av = *(const float4*)(g_attn + ((size_t)ab * H_ + h) * K_ + jbase + k0 + ajq);
        As[ajq+0][ab]=av.x; As[ajq+1][ab]=av.y; As[ajq+2][ab]=av.z; As[ajq+3][ab]=av.w;
#pragma unroll
        for (int p = 0; p < 4; p++) {
            int id = t + p * 256;
            int jr = id >> 5, dc = (id & 31) * 4;
            *(float4*)&Bs[jr][dc] =
                *(const float4*)(g_vproj + (size_t)(jbase + k0 + jr) * D_ + h * HD_ + dc);
        }
        __syncthreads();
#pragma unroll
        for (int kk = 0; kk < 32; kk++) {
            float a[4], b[4];
            *(float4*)&a[0] = *(const float4*)&As[kk][rm];
            *(float4*)&b[0] = *(const float4*)&Bs[kk][rn];
#pragma unroll
            for (int i = 0; i < 4; i++)
#pragma unroll
                for (int j = 0; j < 4; j++)
                    acc[i][j] += a[i] * b[j];
        }
        __syncthreads();
    }
#pragma unroll
    for (int i = 0; i < 4; i++)
#pragma unroll
        for (int j = 0; j < 4; j++)
            g_ctx_part[((size_t)sp * B_ + rm + i) * D_ + h * HD_ + rn + j] = acc[i][j];
}

__global__ void k_ctxred() {
    int i = blockIdx.x * blockDim.x + threadIdx.x;  // 32768
    float s = 0.0f;
#pragma unroll
    for (int sp = 0; sp < NSPLIT; sp++) s += g_ctx_part[(size_t)sp * B_ * D_ + i];
    g_ctx[i] = s;
}

// ---------------- launch ----------------
extern "C" void kernel_launch(void* const* d_in, const int* in_sizes, int n_in,
                              void* d_out, int out_size) {
    const float* query  = (const float*)d_in[0];
    const float* buffer = (const float*)d_in[1];
    const float* prio   = (const float*)d_in[2];
    const float* Wq     = (const float*)d_in[3];
    const float* bq     = (const float*)d_in[4];
    const float* Wk     = (const float*)d_in[5];
    const float* bk     = (const float*)d_in[6];
    const float* Wv     = (const float*)d_in[7];
    const float* bv     = (const float*)d_in[8];
    const float* Wo     = (const float*)d_in[9];
    const float* bo     = (const float*)d_in[10];
    float* out = (float*)d_out;   // [0,32768): retrieved, [32768,163840): attn_avg

    // selection
    k_zero16<<<64, 256>>>();
    k_hist16<<<64, 256>>>(prio);
    k_findbin<<<1, 1024>>>();
    k_compact16<<<64, 256>>>(prio);
    k_selfin48<<<1, 256>>>();
    k_rank<<<K_ / 8, 256>>>();

    // K/V projection on tensor cores (tf32 mma.sync)
    k_kvproj_mma<<<dim3(8, 32, 2), 256>>>(buffer, Wk, bk, Wv, bv);

    // attention tail
    k_gemm32<<<8, 256>>>(query, Wq, bq, nullptr, 0);       // q projection
    k_scores<<<dim3(32, 8), 256>>>();
    k_softmax<<<256, 256>>>();
    k_avg<<<512, 256>>>(out + B_ * D_);
    k_ctxpart<<<dim3(8, NSPLIT), 256>>>();
    k_ctxred<<<128, 256>>>();
    k_gemm32<<<8, 256>>>(nullptr, Wo, bo, out, 1);         // output projection
}

// round 6
// speedup vs baseline: 1.2487x; 1.2487x over previous
#include <cuda_runtime.h>
#include <math.h>
#include <stdint.h>

// Problem constants (fixed by the dataset)
#define B_   32
#define D_   1024
#define N_   65536
#define K_   4096
#define H_   8
#define HD_  128
#define NSPLIT 16

typedef unsigned long long u64;
typedef unsigned int       u32;

// ---------------- scratch (static device globals; no allocation) -------------
__device__ u32  g_hist16[65536];
__device__ int  g_T16;
__device__ int  g_cumAbove;
__device__ int  g_num_cand;
__device__ int  g_sel_count;
__device__ u64  g_cand[N_];
__device__ u64  g_sel_ck[K_];
__device__ int  g_sorted_idx[K_];
__device__ float g_kproj[K_ * D_];
__device__ float g_vproj[K_ * D_];
__device__ float g_qproj[B_ * D_];
__device__ float g_attn[B_ * H_ * K_];
__device__ float g_ctx_part[NSPLIT * B_ * D_];
__device__ float g_ctx[B_ * D_];

__device__ __forceinline__ u32 f2tf32(float f) {
    u32 u;
    asm("cvt.rna.tf32.f32 %0, %1;" : "=r"(u) : "f"(f));
    return u;
}

// m16n8k8 tf32 MMA (base PTX, sm_80+; no sm_103a-gated features)
__device__ __forceinline__ void mma_tf32(
    float& c0, float& c1, float& c2, float& c3,
    u32 a0, u32 a1, u32 a2, u32 a3, u32 b0, u32 b1)
{
    asm volatile(
        "mma.sync.aligned.m16n8k8.row.col.f32.tf32.tf32.f32 "
        "{%0,%1,%2,%3}, {%4,%5,%6,%7}, {%8,%9}, {%0,%1,%2,%3};"
        : "+f"(c0), "+f"(c1), "+f"(c2), "+f"(c3)
        : "r"(a0), "r"(a1), "r"(a2), "r"(a3), "r"(b0), "r"(b1));
}

// Composite key: (monotone(float) << 32) | (0xFFFFFFFF - index)
// Descending composite order == (value desc, index asc) == jax.lax.top_k order.
__device__ __forceinline__ u64 make_ck(float f, int i) {
    u32 x = __float_as_uint(f);
    u32 t = (x & 0x80000000u) ? ~x : (x | 0x80000000u);
    return ((u64)t << 32) | (u32)(0xFFFFFFFFu - (u32)i);
}

// ---------------- selection ----------------
__global__ void k_zero16() {
    int stride = gridDim.x * blockDim.x;
    for (int i = blockIdx.x * blockDim.x + threadIdx.x; i < 65536; i += stride)
        g_hist16[i] = 0;
    if (blockIdx.x == 0 && threadIdx.x == 0) { g_num_cand = 0; g_sel_count = 0; }
}

__global__ void k_hist16(const float* __restrict__ prio) {
    int stride = gridDim.x * blockDim.x;
    for (int i = blockIdx.x * blockDim.x + threadIdx.x; i < N_; i += stride) {
        u64 ck = make_ck(prio[i], i);
        atomicAdd(&g_hist16[(u32)(ck >> 48)], 1u);
    }
}

// Single CTA, 1024 threads: find the 16-bit threshold bin by descending scan.
__global__ void k_findbin() {
    __shared__ u32 strip[1024];
    int t = threadIdx.x;
    int base = 65535 - t * 64;
    u32 s = 0;
    for (int i = 0; i < 64; i++) s += g_hist16[base - i];
    strip[t] = s;
    __syncthreads();
    if (t == 0) {
        u32 cum = 0; int st = 1023;
        for (int i = 0; i < 1024; i++) {
            if (cum + strip[i] >= (u32)K_) { st = i; break; }
            cum += strip[i];
        }
        int b = 65535 - st * 64;
        for (int i = 0; i < 64; i++) {
            u32 h = g_hist16[b - i];
            if (cum + h >= (u32)K_) { g_T16 = b - i; g_cumAbove = (int)cum; break; }
            cum += h;
        }
    }
}

__global__ void k_compact16(const float* __restrict__ prio) {
    int T16 = g_T16;
    int stride = gridDim.x * blockDim.x;
    for (int i = blockIdx.x * blockDim.x + threadIdx.x; i < N_; i += stride) {
        u64 ck = make_ck(prio[i], i);
        int k16 = (int)(u32)(ck >> 48);
        if (k16 > T16) {
            int p = atomicAdd(&g_sel_count, 1);
            g_sel_ck[p] = ck;
        } else if (k16 == T16) {
            int p = atomicAdd(&g_num_cand, 1);
            g_cand[p] = ck;
        }
    }
}

// Single CTA: refine the low 48 bits among the (tiny) candidate set.
__global__ void k_selfin48() {
    __shared__ u64 sc[4096];
    __shared__ u32 hist[256];
    __shared__ u64 s_pref;
    __shared__ int s_R;
    int t = threadIdx.x;  // 256
    int nc = g_num_cand;
    bool inSm = (nc <= 4096);
    if (inSm) for (int i = t; i < nc; i += 256) sc[i] = g_cand[i];
    if (t == 0) {
        s_pref = ((u64)(u32)g_T16) << 48;
        s_R = K_ - g_cumAbove;
    }
    __syncthreads();
    for (int shift = 40; shift >= 0; shift -= 8) {
        hist[t] = 0;
        __syncthreads();
        u64 pref  = s_pref;
        u64 hmask = (~0ULL) << (shift + 8);
        for (int i = t; i < nc; i += 256) {
            u64 ck = inSm ? sc[i] : g_cand[i];
            if ((ck & hmask) == pref)
                atomicAdd(&hist[(u32)(ck >> shift) & 0xFFu], 1u);
        }
        __syncthreads();
        if (t == 0) {
            int R = s_R, cum = 0, b = 0;
            for (int bb = 255; bb >= 0; bb--) {
                if (cum + (int)hist[bb] >= R) { b = bb; break; }
                cum += (int)hist[bb];
            }
            s_pref = pref | (((u64)(u32)b) << shift);
            s_R = R - cum;
        }
        __syncthreads();
    }
    u64 T = s_pref;
    for (int i = t; i < nc; i += 256) {
        u64 ck = inSm ? sc[i] : g_cand[i];
        if (ck >= T) {
            int p = atomicAdd(&g_sel_count, 1);
            g_sel_ck[p] = ck;
        }
    }
}

// Rank sort: one warp per selected element, pairwise count of larger keys.
__global__ void k_rank() {
    __shared__ u64 s_ck[K_];  // 32 KB
    int t = threadIdx.x;
    for (int i = t; i < K_; i += blockDim.x) s_ck[i] = g_sel_ck[i];
    __syncthreads();
    int warp = t >> 5, lane = t & 31;
    int i = blockIdx.x * 8 + warp;
    u64 my = s_ck[i];
    int cnt = 0;
    for (int j = lane; j < K_; j += 32)
        cnt += (s_ck[j] > my) ? 1 : 0;
#pragma unroll
    for (int o = 16; o > 0; o >>= 1) cnt += __shfl_down_sync(0xFFFFFFFFu, cnt, o);
    if (lane == 0)
        g_sorted_idx[cnt] = (int)(0xFFFFFFFFu - (u32)(my & 0xFFFFFFFFull));
}

// ============ K/V projection via mma.sync tf32 (m16n8k8) ============
// CTA tile 128x128, 8 warps, warp tile 64x32 (4x4 frags of 16x8).
// Round-4 layouts + vectorized STS.128 staging (proven), now DOUBLE-BUFFERED
// in dynamic smem with ONE __syncthreads per K=16 chunk.
#define KV_CH 16
#define KV_NCH (D_ / KV_CH)   // 64
#define KV_A_WORDS (128 * 20)
#define KV_B_WORDS (16 * 136)
#define KV_SMEM_BYTES (2 * (KV_A_WORDS + KV_B_WORDS) * 4)   // 37888 < 48KB

__global__ void __launch_bounds__(256, 2)
k_kvproj_mma(const float* __restrict__ buffer,
             const float* __restrict__ Wk, const float* __restrict__ bk,
             const float* __restrict__ Wv, const float* __restrict__ bv)
{
    extern __shared__ u32 dsm[];
    // buffers: [buf][...]
    u32 (*As0)[20]  = (u32(*)[20]) (dsm);
    u32 (*As1)[20]  = (u32(*)[20]) (dsm + KV_A_WORDS);
    u32 (*Bs0)[136] = (u32(*)[136])(dsm + 2 * KV_A_WORDS);
    u32 (*Bs1)[136] = (u32(*)[136])(dsm + 2 * KV_A_WORDS + KV_B_WORDS);

    const float* W    = blockIdx.z ? Wv : Wk;
    const float* bias = blockIdx.z ? bv : bk;
    float* out        = blockIdx.z ? g_vproj : g_kproj;
    int m0 = blockIdx.y * 128;
    int n0 = blockIdx.x * 128;

    int t    = threadIdx.x;
    int lane = t & 31, wid = t >> 5;
    int grp  = lane >> 2, qid = lane & 3;
    int wm   = (wid >> 2) * 64;   // 0 / 64
    int wn   = (wid & 3) * 32;    // 0 / 32 / 64 / 96

    // staging assignments (identical to round-4)
    int aRow = t >> 1, aCol = (t & 1) * 8;          // A: 128 rows x 16 k
    int bRow = t >> 4, bCol = (t & 15) * 8;         // B: 16 k x 128 n
    const float* aPtr = buffer + (size_t)g_sorted_idx[m0 + aRow] * D_ + aCol;
    const float* bPtr = W + (size_t)bRow * D_ + n0 + bCol;

    float acc[4][4][4];
#pragma unroll
    for (int i = 0; i < 4; i++)
#pragma unroll
        for (int j = 0; j < 4; j++)
#pragma unroll
            for (int q = 0; q < 4; q++) acc[i][j][q] = 0.0f;

    float4 pa0, pa1, pb0, pb1;

#define KV_LOAD(c) do { \
    int _ko = (c) * KV_CH; \
    pa0 = *(const float4*)(aPtr + _ko); \
    pa1 = *(const float4*)(aPtr + _ko + 4); \
    pb0 = *(const float4*)(bPtr + (size_t)_ko * D_); \
    pb1 = *(const float4*)(bPtr + (size_t)_ko * D_ + 4); \
} while (0)

#define KV_STORE(Asd, Bsd) do { \
    uint4 wa0 = make_uint4(f2tf32(pa0.x), f2tf32(pa0.y), f2tf32(pa0.z), f2tf32(pa0.w)); \
    uint4 wa1 = make_uint4(f2tf32(pa1.x), f2tf32(pa1.y), f2tf32(pa1.z), f2tf32(pa1.w)); \
    uint4 wb0 = make_uint4(f2tf32(pb0.x), f2tf32(pb0.y), f2tf32(pb0.z), f2tf32(pb0.w)); \
    uint4 wb1 = make_uint4(f2tf32(pb1.x), f2tf32(pb1.y), f2tf32(pb1.z), f2tf32(pb1.w)); \
    *(uint4*)&(Asd)[aRow][aCol]     = wa0; \
    *(uint4*)&(Asd)[aRow][aCol + 4] = wa1; \
    *(uint4*)&(Bsd)[bRow][bCol]     = wb0; \
    *(uint4*)&(Bsd)[bRow][bCol + 4] = wb1; \
} while (0)

    KV_LOAD(0);
    KV_STORE(As0, Bs0);
    __syncthreads();
    KV_LOAD(1);

    for (int c = 0; c < KV_NCH; c++) {
        const u32 (*As)[20]  = (c & 1) ? As1 : As0;
        const u32 (*Bs)[136] = (c & 1) ? Bs1 : Bs0;
        // compute: 2 k-steps of 8 (round-4 fragment mapping)
#pragma unroll
        for (int kk = 0; kk < 16; kk += 8) {
            u32 af[4][4], bf[4][2];
#pragma unroll
            for (int mf = 0; mf < 4; mf++) {
                int r = wm + mf * 16 + grp;
                af[mf][0] = As[r][kk + qid];
                af[mf][1] = As[r + 8][kk + qid];
                af[mf][2] = As[r][kk + qid + 4];
                af[mf][3] = As[r + 8][kk + qid + 4];
            }
#pragma unroll
            for (int nf = 0; nf < 4; nf++) {
                int n = wn + nf * 8 + grp;
                bf[nf][0] = Bs[kk + qid][n];
                bf[nf][1] = Bs[kk + qid + 4][n];
            }
#pragma unroll
            for (int mf = 0; mf < 4; mf++)
#pragma unroll
                for (int nf = 0; nf < 4; nf++)
                    mma_tf32(acc[mf][nf][0], acc[mf][nf][1], acc[mf][nf][2], acc[mf][nf][3],
                             af[mf][0], af[mf][1], af[mf][2], af[mf][3],
                             bf[nf][0], bf[nf][1]);
        }
        if (c + 1 < KV_NCH) {
            if ((c + 1) & 1) KV_STORE(As1, Bs1); else KV_STORE(As0, Bs0);
            __syncthreads();
            if (c + 2 < KV_NCH) KV_LOAD(c + 2);
        }
    }

    // epilogue: D[m][n] + bias[n]
#pragma unroll
    for (int mf = 0; mf < 4; mf++) {
#pragma unroll
        for (int nf = 0; nf < 4; nf++) {
            int n = n0 + wn + nf * 8 + 2 * qid;
            float bv0 = bias[n], bv1 = bias[n + 1];
            int r0 = m0 + wm + mf * 16 + grp;
            float2 v0 = make_float2(acc[mf][nf][0] + bv0, acc[mf][nf][1] + bv1);
            float2 v1 = make_float2(acc[mf][nf][2] + bv0, acc[mf][nf][3] + bv1);
            *(float2*)(out + (size_t)r0 * D_ + n)       = v0;
            *(float2*)(out + (size_t)(r0 + 8) * D_ + n) = v1;
        }
    }
#undef KV_LOAD
#undef KV_STORE
}

// ---------------- M=32 GEMM (q proj: mode 0, out proj: mode 1) --------------
__global__ void k_gemm32(const float* __restrict__ Aext,
                         const float* __restrict__ W,
                         const float* __restrict__ bias,
                         float* __restrict__ outext, int mode)
{
    const float* A = (mode == 0) ? Aext : g_ctx;
    float* out     = (mode == 0) ? g_qproj : outext;
    int n0 = blockIdx.x * 128;

    __shared__ float As[32][36];   // [k][b]
    __shared__ float Bs[32][128];  // [k][n]
    int t = threadIdx.x;
    float acc[4][4] = {};
    int rm = (t >> 5) * 4, rn = (t & 31) * 4;
    int ab = t >> 3, akq = (t & 7) * 4;

    for (int k0 = 0; k0 < D_; k0 += 32) {
        float4 av = *(const float4*)(A + (size_t)ab * D_ + k0 + akq);
        As[akq+0][ab]=av.x; As[akq+1][ab]=av.y; As[akq+2][ab]=av.z; As[akq+3][ab]=av.w;
#pragma unroll
        for (int p = 0; p < 4; p++) {
            int id = t + p * 256;
            int br = id >> 5, bc = (id & 31) * 4;
            *(float4*)&Bs[br][bc] = *(const float4*)(W + (size_t)(k0 + br) * D_ + n0 + bc);
        }
        __syncthreads();
#pragma unroll
        for (int kk = 0; kk < 32; kk++) {
            float a[4], b[4];
            *(float4*)&a[0] = *(const float4*)&As[kk][rm];
            *(float4*)&b[0] = *(const float4*)&Bs[kk][rn];
#pragma unroll
            for (int i = 0; i < 4; i++)
#pragma unroll
                for (int j = 0; j < 4; j++)
                    acc[i][j] += a[i] * b[j];
        }
        __syncthreads();
    }
#pragma unroll
    for (int i = 0; i < 4; i++) {
        float* op = out + (size_t)(rm + i) * D_ + n0 + rn;
#pragma unroll
        for (int j = 0; j < 4; j++)
            op[j] = acc[i][j] + bias[n0 + rn + j];
    }
}

// ---------------- scores[b,h,j] = scale * q[b,h,:] . k[j,h,:] ---------------
__global__ void k_scores() {
    int j0 = blockIdx.x * 128;
    int h  = blockIdx.y;
    __shared__ float As[32][36];   // [d][b]
    __shared__ float Bs[32][132];  // [d][j]
    int t = threadIdx.x;
    float acc[4][4] = {};
    int rm = (t >> 5) * 4, rn = (t & 31) * 4;
    int ab = t >> 3, akq = (t & 7) * 4;

    for (int d0 = 0; d0 < HD_; d0 += 32) {
        float4 av = *(const float4*)(g_qproj + (size_t)ab * D_ + h * HD_ + d0 + akq);
        As[akq+0][ab]=av.x; As[akq+1][ab]=av.y; As[akq+2][ab]=av.z; As[akq+3][ab]=av.w;
#pragma unroll
        for (int p = 0; p < 4; p++) {
            int id = t + p * 256;
            int jr = id >> 3, dq = (id & 7) * 4;
            float4 bvv = *(const float4*)(g_kproj + (size_t)(j0 + jr) * D_ + h * HD_ + d0 + dq);
            Bs[dq+0][jr]=bvv.x; Bs[dq+1][jr]=bvv.y; Bs[dq+2][jr]=bvv.z; Bs[dq+3][jr]=bvv.w;
        }
        __syncthreads();
#pragma unroll
        for (int kk = 0; kk < 32; kk++) {
            float a[4], b[4];
            *(float4*)&a[0] = *(const float4*)&As[kk][rm];
            *(float4*)&b[0] = *(const float4*)&Bs[kk][rn];
#pragma unroll
            for (int i = 0; i < 4; i++)
#pragma unroll
                for (int j = 0; j < 4; j++)
                    acc[i][j] += a[i] * b[j];
        }
        __syncthreads();
    }
    const float scale = 0.08838834764831845f;  // 128^-0.5
#pragma unroll
    for (int i = 0; i < 4; i++)
#pragma unroll
        for (int j = 0; j < 4; j++)
            g_attn[((size_t)(rm + i) * H_ + h) * K_ + j0 + rn + j] = acc[i][j] * scale;
}

// ---------------- softmax over j (in place), one CTA per (b,h) row ----------
__global__ void k_softmax() {
    int row = blockIdx.x;
    float* p = g_attn + (size_t)row * K_;
    __shared__ float sd[K_];
    __shared__ float red[256];
    int t = threadIdx.x;
    float mx = -1e30f;
    for (int i = t; i < K_; i += 256) { float v = p[i]; sd[i] = v; mx = fmaxf(mx, v); }
    red[t] = mx; __syncthreads();
    for (int o = 128; o > 0; o >>= 1) { if (t < o) red[t] = fmaxf(red[t], red[t + o]); __syncthreads(); }
    mx = red[0]; __syncthreads();
    float sum = 0.0f;
    for (int i = t; i < K_; i += 256) { float e = expf(sd[i] - mx); sd[i] = e; sum += e; }
    red[t] = sum; __syncthreads();
    for (int o = 128; o > 0; o >>= 1) { if (t < o) red[t] += red[t + o]; __syncthreads(); }
    float inv = 1.0f / red[0];
    for (int i = t; i < K_; i += 256) p[i] = sd[i] * inv;
}

// ---------------- attn_avg = mean over heads -> d_out[32768:] ---------------
__global__ void k_avg(float* __restrict__ out2) {
    int idx = blockIdx.x * blockDim.x + threadIdx.x;  // 131072 total
    int b = idx >> 12, j = idx & 4095;
    float s = 0.0f;
#pragma unroll
    for (int h = 0; h < H_; h++) s += g_attn[((size_t)b * H_ + h) * K_ + j];
    out2[(size_t)b * K_ + j] = s * 0.125f;
}

// ---------------- ctx partials: attn[b,h,:] @ v[:,h,:] over j-split ---------
__global__ void k_ctxpart() {
    int h  = blockIdx.x;       // 8
    int sp = blockIdx.y;       // 16
    int jbase = sp * (K_ / NSPLIT);   // 256 j per split
    __shared__ float As[32][36];    // [j][b]
    __shared__ float Bs[32][128];   // [j][d]
    int t = threadIdx.x;
    float acc[4][4] = {};
    int rm = (t >> 5) * 4, rn = (t & 31) * 4;
    int ab = t >> 3, ajq = (t & 7) * 4;

    for (int k0 = 0; k0 < K_ / NSPLIT; k0 += 32) {
        float4 av = *(const float4*)(g_attn + ((size_t)ab * H_ + h) * K_ + jbase + k0 + ajq);
        As[ajq+0][ab]=av.x; As[ajq+1][ab]=av.y; As[ajq+2][ab]=av.z; As[ajq+3][ab]=av.w;
#pragma unroll
        for (int p = 0; p < 4; p++) {
            int id = t + p * 256;
            int jr = id >> 5, dc = (id & 31) * 4;
            *(float4*)&Bs[jr][dc] =
                *(const float4*)(g_vproj + (size_t)(jbase + k0 + jr) * D_ + h * HD_ + dc);
        }
        __syncthreads();
#pragma unroll
        for (int kk = 0; kk < 32; kk++) {
            float a[4], b[4];
            *(float4*)&a[0] = *(const float4*)&As[kk][rm];
            *(float4*)&b[0] = *(const float4*)&Bs[kk][rn];
#pragma unroll
            for (int i = 0; i < 4; i++)
#pragma unroll
                for (int j = 0; j < 4; j++)
                    acc[i][j] += a[i] * b[j];
        }
        __syncthreads();
    }
#pragma unroll
    for (int i = 0; i < 4; i++)
#pragma unroll
        for (int j = 0; j < 4; j++)
            g_ctx_part[((size_t)sp * B_ + rm + i) * D_ + h * HD_ + rn + j] = acc[i][j];
}

__global__ void k_ctxred() {
    int i = blockIdx.x * blockDim.x + threadIdx.x;  // 32768
    float s = 0.0f;
#pragma unroll
    for (int sp = 0; sp < NSPLIT; sp++) s += g_ctx_part[(size_t)sp * B_ * D_ + i];
    g_ctx[i] = s;
}

// ---------------- launch ----------------
extern "C" void kernel_launch(void* const* d_in, const int* in_sizes, int n_in,
                              void* d_out, int out_size) {
    const float* query  = (const float*)d_in[0];
    const float* buffer = (const float*)d_in[1];
    const float* prio   = (const float*)d_in[2];
    const float* Wq     = (const float*)d_in[3];
    const float* bq     = (const float*)d_in[4];
    const float* Wk     = (const float*)d_in[5];
    const float* bk     = (const float*)d_in[6];
    const float* Wv     = (const float*)d_in[7];
    const float* bv     = (const float*)d_in[8];
    const float* Wo     = (const float*)d_in[9];
    const float* bo     = (const float*)d_in[10];
    float* out = (float*)d_out;   // [0,32768): retrieved, [32768,163840): attn_avg

    // selection
    k_zero16<<<64, 256>>>();
    k_hist16<<<64, 256>>>(prio);
    k_findbin<<<1, 1024>>>();
    k_compact16<<<64, 256>>>(prio);
    k_selfin48<<<1, 256>>>();
    k_rank<<<K_ / 8, 256>>>();

    // K/V projection on tensor cores (tf32 mma.sync, double-buffered)
    k_kvproj_mma<<<dim3(8, 32, 2), 256, KV_SMEM_BYTES>>>(buffer, Wk, bk, Wv, bv);

    // attention tail
    k_gemm32<<<8, 256>>>(query, Wq, bq, nullptr, 0);       // q projection
    k_scores<<<dim3(32, 8), 256>>>();
    k_softmax<<<256, 256>>>();
    k_avg<<<512, 256>>>(out + B_ * D_);
    k_ctxpart<<<dim3(8, NSPLIT), 256>>>();
    k_ctxred<<<128, 256>>>();
    k_gemm32<<<8, 256>>>(nullptr, Wo, bo, out, 1);         // output projection
}

// round 7
// speedup vs baseline: 1.4760x; 1.1820x over previous
#include <cuda_runtime.h>
#include <cuda_fp16.h>
#include <math.h>
#include <stdint.h>

// Problem constants (fixed by the dataset)
#define B_   32
#define D_   1024
#define N_   65536
#define K_   4096
#define H_   8
#define HD_  128
#define NSPLIT 16

typedef unsigned long long u64;
typedef unsigned int       u32;

// ---------------- scratch (static device globals; no allocation) -------------
__device__ u32  g_hist16[65536];
__device__ int  g_T16;
__device__ int  g_cumAbove;
__device__ int  g_num_cand;
__device__ int  g_sel_count;
__device__ u64  g_cand[N_];
__device__ u64  g_sel_ck[K_];
__device__ int  g_sorted_idx[K_];
__device__ float g_kproj[K_ * D_];
__device__ float g_vproj[K_ * D_];
__device__ float g_qproj[B_ * D_];
__device__ float g_attn[B_ * H_ * K_];
__device__ float g_ctx_part[NSPLIT * B_ * D_];
__device__ float g_ctx[B_ * D_];

// pack two floats into fp16x2 (lo = first arg in low half)
__device__ __forceinline__ u32 f2h2(float lo, float hi) {
    __half2 h = __floats2half2_rn(lo, hi);
    return *(u32*)&h;
}

// m16n8k16 fp16 MMA, fp32 accum (base PTX, sm_80+; no sm_103a-gated features)
__device__ __forceinline__ void mma_f16(
    float& c0, float& c1, float& c2, float& c3,
    u32 a0, u32 a1, u32 a2, u32 a3, u32 b0, u32 b1)
{
    asm volatile(
        "mma.sync.aligned.m16n8k16.row.col.f32.f16.f16.f32 "
        "{%0,%1,%2,%3}, {%4,%5,%6,%7}, {%8,%9}, {%0,%1,%2,%3};"
        : "+f"(c0), "+f"(c1), "+f"(c2), "+f"(c3)
        : "r"(a0), "r"(a1), "r"(a2), "r"(a3), "r"(b0), "r"(b1));
}

// Composite key: (monotone(float) << 32) | (0xFFFFFFFF - index)
// Descending composite order == (value desc, index asc) == jax.lax.top_k order.
__device__ __forceinline__ u64 make_ck(float f, int i) {
    u32 x = __float_as_uint(f);
    u32 t = (x & 0x80000000u) ? ~x : (x | 0x80000000u);
    return ((u64)t << 32) | (u32)(0xFFFFFFFFu - (u32)i);
}

// ---------------- selection ----------------
__global__ void k_zero16() {
    int stride = gridDim.x * blockDim.x;
    for (int i = blockIdx.x * blockDim.x + threadIdx.x; i < 65536; i += stride)
        g_hist16[i] = 0;
    if (blockIdx.x == 0 && threadIdx.x == 0) { g_num_cand = 0; g_sel_count = 0; }
}

__global__ void k_hist16(const float* __restrict__ prio) {
    int stride = gridDim.x * blockDim.x;
    for (int i = blockIdx.x * blockDim.x + threadIdx.x; i < N_; i += stride) {
        u64 ck = make_ck(prio[i], i);
        atomicAdd(&g_hist16[(u32)(ck >> 48)], 1u);
    }
}

// Single CTA, 1024 threads: find the 16-bit threshold bin by descending scan.
__global__ void k_findbin() {
    __shared__ u32 strip[1024];
    int t = threadIdx.x;
    int base = 65535 - t * 64;
    u32 s = 0;
    for (int i = 0; i < 64; i++) s += g_hist16[base - i];
    strip[t] = s;
    __syncthreads();
    if (t == 0) {
        u32 cum = 0; int st = 1023;
        for (int i = 0; i < 1024; i++) {
            if (cum + strip[i] >= (u32)K_) { st = i; break; }
            cum += strip[i];
        }
        int b = 65535 - st * 64;
        for (int i = 0; i < 64; i++) {
            u32 h = g_hist16[b - i];
            if (cum + h >= (u32)K_) { g_T16 = b - i; g_cumAbove = (int)cum; break; }
            cum += h;
        }
    }
}

__global__ void k_compact16(const float* __restrict__ prio) {
    int T16 = g_T16;
    int stride = gridDim.x * blockDim.x;
    for (int i = blockIdx.x * blockDim.x + threadIdx.x; i < N_; i += stride) {
        u64 ck = make_ck(prio[i], i);
        int k16 = (int)(u32)(ck >> 48);
        if (k16 > T16) {
            int p = atomicAdd(&g_sel_count, 1);
            g_sel_ck[p] = ck;
        } else if (k16 == T16) {
            int p = atomicAdd(&g_num_cand, 1);
            g_cand[p] = ck;
        }
    }
}

// Single CTA: refine the low 48 bits among the (tiny) candidate set.
__global__ void k_selfin48() {
    __shared__ u64 sc[4096];
    __shared__ u32 hist[256];
    __shared__ u64 s_pref;
    __shared__ int s_R;
    int t = threadIdx.x;  // 256
    int nc = g_num_cand;
    bool inSm = (nc <= 4096);
    if (inSm) for (int i = t; i < nc; i += 256) sc[i] = g_cand[i];
    if (t == 0) {
        s_pref = ((u64)(u32)g_T16) << 48;
        s_R = K_ - g_cumAbove;
    }
    __syncthreads();
    for (int shift = 40; shift >= 0; shift -= 8) {
        hist[t] = 0;
        __syncthreads();
        u64 pref  = s_pref;
        u64 hmask = (~0ULL) << (shift + 8);
        for (int i = t; i < nc; i += 256) {
            u64 ck = inSm ? sc[i] : g_cand[i];
            if ((ck & hmask) == pref)
                atomicAdd(&hist[(u32)(ck >> shift) & 0xFFu], 1u);
        }
        __syncthreads();
        if (t == 0) {
            int R = s_R, cum = 0, b = 0;
            for (int bb = 255; bb >= 0; bb--) {
                if (cum + (int)hist[bb] >= R) { b = bb; break; }
                cum += (int)hist[bb];
            }
            s_pref = pref | (((u64)(u32)b) << shift);
            s_R = R - cum;
        }
        __syncthreads();
    }
    u64 T = s_pref;
    for (int i = t; i < nc; i += 256) {
        u64 ck = inSm ? sc[i] : g_cand[i];
        if (ck >= T) {
            int p = atomicAdd(&g_sel_count, 1);
            g_sel_ck[p] = ck;
        }
    }
}

// Rank sort: one warp per selected element, pairwise count of larger keys.
__global__ void k_rank() {
    __shared__ u64 s_ck[K_];  // 32 KB
    int t = threadIdx.x;
    for (int i = t; i < K_; i += blockDim.x) s_ck[i] = g_sel_ck[i];
    __syncthreads();
    int warp = t >> 5, lane = t & 31;
    int i = blockIdx.x * 8 + warp;
    u64 my = s_ck[i];
    int cnt = 0;
    for (int j = lane; j < K_; j += 32)
        cnt += (s_ck[j] > my) ? 1 : 0;
#pragma unroll
    for (int o = 16; o > 0; o >>= 1) cnt += __shfl_down_sync(0xFFFFFFFFu, cnt, o);
    if (lane == 0)
        g_sorted_idx[cnt] = (int)(0xFFFFFFFFu - (u32)(my & 0xFFFFFFFFull));
}

// ============ K/V projection via mma.sync fp16 (m16n8k16) ============
// CTA tile 128x128, 8 warps, warp tile 64x32 (4x4 frags of 16x8).
// Double-buffered, one __syncthreads per K=16 chunk.
// fp16 pairs packed along K:
//   As[row][kw]  (kw = k/2), stride 12  -> frag loads conflict-free
//   Bs[kw][n],              stride 136 -> frag loads conflict-free
#define KV_CH 16
#define KV_NCH (D_ / KV_CH)   // 64
#define KV_A_WORDS (128 * 12)
#define KV_B_WORDS (8 * 136)
#define KV_SMEM_BYTES (2 * (KV_A_WORDS + KV_B_WORDS) * 4)   // 20992

__global__ void __launch_bounds__(256, 2)
k_kvproj_mma(const float* __restrict__ buffer,
             const float* __restrict__ Wk, const float* __restrict__ bk,
             const float* __restrict__ Wv, const float* __restrict__ bv)
{
    extern __shared__ u32 dsm[];
    u32 (*As0)[12]  = (u32(*)[12]) (dsm);
    u32 (*As1)[12]  = (u32(*)[12]) (dsm + KV_A_WORDS);
    u32 (*Bs0)[136] = (u32(*)[136])(dsm + 2 * KV_A_WORDS);
    u32 (*Bs1)[136] = (u32(*)[136])(dsm + 2 * KV_A_WORDS + KV_B_WORDS);

    const float* W    = blockIdx.z ? Wv : Wk;
    const float* bias = blockIdx.z ? bv : bk;
    float* out        = blockIdx.z ? g_vproj : g_kproj;
    int m0 = blockIdx.y * 128;
    int n0 = blockIdx.x * 128;

    int t    = threadIdx.x;
    int lane = t & 31, wid = t >> 5;
    int grp  = lane >> 2, qid = lane & 3;
    int wm   = (wid >> 2) * 64;   // 0 / 64
    int wn   = (wid & 3) * 32;    // 0 / 32 / 64 / 96

    // A staging: thread t -> row aRow = t>>1, k-offset aCol = (t&1)*8 (8 floats)
    int aRow = t >> 1, aCol = (t & 1) * 8;
    // B staging: thread t -> k-pair kp = t>>5 (rows 2kp, 2kp+1), n4 = (t&31)*4
    int kp = t >> 5, n4 = (t & 31) * 4;

    const float* aPtr  = buffer + (size_t)g_sorted_idx[m0 + aRow] * D_ + aCol;
    const float* bPtr0 = W + (size_t)(2 * kp)     * D_ + n0 + n4;
    const float* bPtr1 = W + (size_t)(2 * kp + 1) * D_ + n0 + n4;

    float acc[4][4][4];
#pragma unroll
    for (int i = 0; i < 4; i++)
#pragma unroll
        for (int j = 0; j < 4; j++)
#pragma unroll
            for (int q = 0; q < 4; q++) acc[i][j][q] = 0.0f;

    float4 pa0, pa1, pb0, pb1;

#define KV_LOAD(c) do { \
    int _ko = (c) * KV_CH; \
    pa0 = *(const float4*)(aPtr + _ko); \
    pa1 = *(const float4*)(aPtr + _ko + 4); \
    pb0 = *(const float4*)(bPtr0 + (size_t)_ko * D_); \
    pb1 = *(const float4*)(bPtr1 + (size_t)_ko * D_); \
} while (0)

#define KV_STORE(Asd, Bsd) do { \
    uint4 wa = make_uint4(f2h2(pa0.x, pa0.y), f2h2(pa0.z, pa0.w), \
                          f2h2(pa1.x, pa1.y), f2h2(pa1.z, pa1.w)); \
    uint4 wb = make_uint4(f2h2(pb0.x, pb1.x), f2h2(pb0.y, pb1.y), \
                          f2h2(pb0.z, pb1.z), f2h2(pb0.w, pb1.w)); \
    *(uint4*)&(Asd)[aRow][(aCol >> 1)] = wa; \
    *(uint4*)&(Bsd)[kp][n4]            = wb; \
} while (0)

    KV_LOAD(0);
    KV_STORE(As0, Bs0);
    __syncthreads();
    KV_LOAD(1);

    for (int c = 0; c < KV_NCH; c++) {
        const u32 (*As)[12]  = (c & 1) ? As1 : As0;
        const u32 (*Bs)[136] = (c & 1) ? Bs1 : Bs0;
        // one K=16 step: 16 MMAs
        u32 af[4][4], bf[4][2];
#pragma unroll
        for (int mf = 0; mf < 4; mf++) {
            int r = wm + mf * 16 + grp;
            af[mf][0] = As[r][qid];
            af[mf][1] = As[r + 8][qid];
            af[mf][2] = As[r][qid + 4];
            af[mf][3] = As[r + 8][qid + 4];
        }
#pragma unroll
        for (int nf = 0; nf < 4; nf++) {
            int n = wn + nf * 8 + grp;
            bf[nf][0] = Bs[qid][n];
            bf[nf][1] = Bs[qid + 4][n];
        }
#pragma unroll
        for (int mf = 0; mf < 4; mf++)
#pragma unroll
            for (int nf = 0; nf < 4; nf++)
                mma_f16(acc[mf][nf][0], acc[mf][nf][1], acc[mf][nf][2], acc[mf][nf][3],
                        af[mf][0], af[mf][1], af[mf][2], af[mf][3],
                        bf[nf][0], bf[nf][1]);
        if (c + 1 < KV_NCH) {
            if ((c + 1) & 1) KV_STORE(As1, Bs1); else KV_STORE(As0, Bs0);
            __syncthreads();
            if (c + 2 < KV_NCH) KV_LOAD(c + 2);
        }
    }

    // epilogue: D[m][n] + bias[n]
#pragma unroll
    for (int mf = 0; mf < 4; mf++) {
#pragma unroll
        for (int nf = 0; nf < 4; nf++) {
            int n = n0 + wn + nf * 8 + 2 * qid;
            float bv0 = bias[n], bv1 = bias[n + 1];
            int r0 = m0 + wm + mf * 16 + grp;
            float2 v0 = make_float2(acc[mf][nf][0] + bv0, acc[mf][nf][1] + bv1);
            float2 v1 = make_float2(acc[mf][nf][2] + bv0, acc[mf][nf][3] + bv1);
            *(float2*)(out + (size_t)r0 * D_ + n)       = v0;
            *(float2*)(out + (size_t)(r0 + 8) * D_ + n) = v1;
        }
    }
#undef KV_LOAD
#undef KV_STORE
}

// ---------------- M=32 GEMM (q proj: mode 0, out proj: mode 1) --------------
__global__ void k_gemm32(const float* __restrict__ Aext,
                         const float* __restrict__ W,
                         const float* __restrict__ bias,
                         float* __restrict__ outext, int mode)
{
    const float* A = (mode == 0) ? Aext : g_ctx;
    float* out     = (mode == 0) ? g_qproj : outext;
    int n0 = blockIdx.x * 128;

    __shared__ float As[32][36];   // [k][b]
    __shared__ float Bs[32][128];  // [k][n]
    int t = threadIdx.x;
    float acc[4][4] = {};
    int rm = (t >> 5) * 4, rn = (t & 31) * 4;
    int ab = t >> 3, akq = (t & 7) * 4;

    for (int k0 = 0; k0 < D_; k0 += 32) {
        float4 av = *(const float4*)(A + (size_t)ab * D_ + k0 + akq);
        As[akq+0][ab]=av.x; As[akq+1][ab]=av.y; As[akq+2][ab]=av.z; As[akq+3][ab]=av.w;
#pragma unroll
        for (int p = 0; p < 4; p++) {
            int id = t + p * 256;
            int br = id >> 5, bc = (id & 31) * 4;
            *(float4*)&Bs[br][bc] = *(const float4*)(W + (size_t)(k0 + br) * D_ + n0 + bc);
        }
        __syncthreads();
#pragma unroll
        for (int kk = 0; kk < 32; kk++) {
            float a[4], b[4];
            *(float4*)&a[0] = *(const float4*)&As[kk][rm];
            *(float4*)&b[0] = *(const float4*)&Bs[kk][rn];
#pragma unroll
            for (int i = 0; i < 4; i++)
#pragma unroll
                for (int j = 0; j < 4; j++)
                    acc[i][j] += a[i] * b[j];
        }
        __syncthreads();
    }
#pragma unroll
    for (int i = 0; i < 4; i++) {
        float* op = out + (size_t)(rm + i) * D_ + n0 + rn;
#pragma unroll
        for (int j = 0; j < 4; j++)
            op[j] = acc[i][j] + bias[n0 + rn + j];
    }
}

// ---------------- scores[b,h,j] = scale * q[b,h,:] . k[j,h,:] ---------------
__global__ void k_scores() {
    int j0 = blockIdx.x * 128;
    int h  = blockIdx.y;
    __shared__ float As[32][36];   // [d][b]
    __shared__ float Bs[32][132];  // [d][j]
    int t = threadIdx.x;
    float acc[4][4] = {};
    int rm = (t >> 5) * 4, rn = (t & 31) * 4;
    int ab = t >> 3, akq = (t & 7) * 4;

    for (int d0 = 0; d0 < HD_; d0 += 32) {
        float4 av = *(const float4*)(g_qproj + (size_t)ab * D_ + h * HD_ + d0 + akq);
        As[akq+0][ab]=av.x; As[akq+1][ab]=av.y; As[akq+2][ab]=av.z; As[akq+3][ab]=av.w;
#pragma unroll
        for (int p = 0; p < 4; p++) {
            int id = t + p * 256;
            int jr = id >> 3, dq = (id & 7) * 4;
            float4 bvv = *(const float4*)(g_kproj + (size_t)(j0 + jr) * D_ + h * HD_ + d0 + dq);
            Bs[dq+0][jr]=bvv.x; Bs[dq+1][jr]=bvv.y; Bs[dq+2][jr]=bvv.z; Bs[dq+3][jr]=bvv.w;
        }
        __syncthreads();
#pragma unroll
        for (int kk = 0; kk < 32; kk++) {
            float a[4], b[4];
            *(float4*)&a[0] = *(const float4*)&As[kk][rm];
            *(float4*)&b[0] = *(const float4*)&Bs[kk][rn];
#pragma unroll
            for (int i = 0; i < 4; i++)
#pragma unroll
                for (int j = 0; j < 4; j++)
                    acc[i][j] += a[i] * b[j];
        }
        __syncthreads();
    }
    const float scale = 0.08838834764831845f;  // 128^-0.5
#pragma unroll
    for (int i = 0; i < 4; i++)
#pragma unroll
        for (int j = 0; j < 4; j++)
            g_attn[((size_t)(rm + i) * H_ + h) * K_ + j0 + rn + j] = acc[i][j] * scale;
}

// ---------------- softmax over j (in place), one CTA per (b,h) row ----------
__global__ void k_softmax() {
    int row = blockIdx.x;
    float* p = g_attn + (size_t)row * K_;
    __shared__ float sd[K_];
    __shared__ float red[256];
    int t = threadIdx.x;
    float mx = -1e30f;
    for (int i = t; i < K_; i += 256) { float v = p[i]; sd[i] = v; mx = fmaxf(mx, v); }
    red[t] = mx; __syncthreads();
    for (int o = 128; o > 0; o >>= 1) { if (t < o) red[t] = fmaxf(red[t], red[t + o]); __syncthreads(); }
    mx = red[0]; __syncthreads();
    float sum = 0.0f;
    for (int i = t; i < K_; i += 256) { float e = expf(sd[i] - mx); sd[i] = e; sum += e; }
    red[t] = sum; __syncthreads();
    for (int o = 128; o > 0; o >>= 1) { if (t < o) red[t] += red[t + o]; __syncthreads(); }
    float inv = 1.0f / red[0];
    for (int i = t; i < K_; i += 256) p[i] = sd[i] * inv;
}

// ---------------- attn_avg = mean over heads -> d_out[32768:] ---------------
__global__ void k_avg(float* __restrict__ out2) {
    int idx = blockIdx.x * blockDim.x + threadIdx.x;  // 131072 total
    int b = idx >> 12, j = idx & 4095;
    float s = 0.0f;
#pragma unroll
    for (int h = 0; h < H_; h++) s += g_attn[((size_t)b * H_ + h) * K_ + j];
    out2[(size_t)b * K_ + j] = s * 0.125f;
}

// ---------------- ctx partials: attn[b,h,:] @ v[:,h,:] over j-split ---------
__global__ void k_ctxpart() {
    int h  = blockIdx.x;       // 8
    int sp = blockIdx.y;       // 16
    int jbase = sp * (K_ / NSPLIT);   // 256 j per split
    __shared__ float As[32][36];    // [j][b]
    __shared__ float Bs[32][128];   // [j][d]
    int t = threadIdx.x;
    float acc[4][4] = {};
    int rm = (t >> 5) * 4, rn = (t & 31) * 4;
    int ab = t >> 3, ajq = (t & 7) * 4;

    for (int k0 = 0; k0 < K_ / NSPLIT; k0 += 32) {
        float4 av = *(const float4*)(g_attn + ((size_t)ab * H_ + h) * K_ + jbase + k0 + ajq);
        As[ajq+0][ab]=av.x; As[ajq+1][ab]=av.y; As[ajq+2][ab]=av.z; As[ajq+3][ab]=av.w;
#pragma unroll
        for (int p = 0; p < 4; p++) {
            int id = t + p * 256;
            int jr = id >> 5, dc = (id & 31) * 4;
            *(float4*)&Bs[jr][dc] =
                *(const float4*)(g_vproj + (size_t)(jbase + k0 + jr) * D_ + h * HD_ + dc);
        }
        __syncthreads();
#pragma unroll
        for (int kk = 0; kk < 32; kk++) {
            float a[4], b[4];
            *(float4*)&a[0] = *(const float4*)&As[kk][rm];
            *(float4*)&b[0] = *(const float4*)&Bs[kk][rn];
#pragma unroll
            for (int i = 0; i < 4; i++)
#pragma unroll
                for (int j = 0; j < 4; j++)
                    acc[i][j] += a[i] * b[j];
        }
        __syncthreads();
    }
#pragma unroll
    for (int i = 0; i < 4; i++)
#pragma unroll
        for (int j = 0; j < 4; j++)
            g_ctx_part[((size_t)sp * B_ + rm + i) * D_ + h * HD_ + rn + j] = acc[i][j];
}

__global__ void k_ctxred() {
    int i = blockIdx.x * blockDim.x + threadIdx.x;  // 32768
    float s = 0.0f;
#pragma unroll
    for (int sp = 0; sp < NSPLIT; sp++) s += g_ctx_part[(size_t)sp * B_ * D_ + i];
    g_ctx[i] = s;
}

// ---------------- launch ----------------
extern "C" void kernel_launch(void* const* d_in, const int* in_sizes, int n_in,
                              void* d_out, int out_size) {
    const float* query  = (const float*)d_in[0];
    const float* buffer = (const float*)d_in[1];
    const float* prio   = (const float*)d_in[2];
    const float* Wq     = (const float*)d_in[3];
    const float* bq     = (const float*)d_in[4];
    const float* Wk     = (const float*)d_in[5];
    const float* bk     = (const float*)d_in[6];
    const float* Wv     = (const float*)d_in[7];
    const float* bv     = (const float*)d_in[8];
    const float* Wo     = (const float*)d_in[9];
    const float* bo     = (const float*)d_in[10];
    float* out = (float*)d_out;   // [0,32768): retrieved, [32768,163840): attn_avg

    // selection
    k_zero16<<<64, 256>>>();
    k_hist16<<<64, 256>>>(prio);
    k_findbin<<<1, 1024>>>();
    k_compact16<<<64, 256>>>(prio);
    k_selfin48<<<1, 256>>>();
    k_rank<<<K_ / 8, 256>>>();

    // K/V projection on tensor cores (fp16 mma.sync m16n8k16, double-buffered)
    k_kvproj_mma<<<dim3(8, 32, 2), 256, KV_SMEM_BYTES>>>(buffer, Wk, bk, Wv, bv);

    // attention tail
    k_gemm32<<<8, 256>>>(query, Wq, bq, nullptr, 0);       // q projection
    k_scores<<<dim3(32, 8), 256>>>();
    k_softmax<<<256, 256>>>();
    k_avg<<<512, 256>>>(out + B_ * D_);
    k_ctxpart<<<dim3(8, NSPLIT), 256>>>();
    k_ctxred<<<128, 256>>>();
    k_gemm32<<<8, 256>>>(nullptr, Wo, bo, out, 1);         // output projection
}